// round 16
// baseline (speedup 1.0000x reference)
#include <cuda_runtime.h>
#include <cstdint>

#define BB 64
#define CC 64
#define HH 128
#define WW 128
#define NSLAB (BB * CC)
#define GRID1 296   // persistent, single wave: 2/SM on 148 SMs (<=2/SM on 152).

// Scratch (allocation-free rule: __device__ globals)
__device__ float    g_cs_e [NSLAB * WW]; // colsum_e [b,c,w]  = sum_h exp(x-m)
__device__ float    g_cs_ey[NSLAB * WW]; // colsum_ey[b,c,w]  = sum_h exp(x-m)*wy[h]
__device__ unsigned g_done;              // monotonic CTA-completion counter

__device__ __forceinline__ void l2_prefetch_64k(const void* p) {
    asm volatile("cp.async.bulk.prefetch.L2.global [%0], %1;"
                 :: "l"(p), "r"(65536));
}

__device__ __forceinline__ uint64_t pol_evict_last() {
    uint64_t p;
    asm("createpolicy.fractional.L2::evict_last.b64 %0, 1.0;" : "=l"(p));
    return p;
}

// 256-bit load with built-in evict_first (direct qualifier is legal for v8.b32
// on sm_103a). Halves LSU issue + address ALU vs 2x LDG.128.
__device__ __forceinline__ void ldg_v8_ef(const void* p, float* v) {
    asm("ld.global.nc.L2::evict_first.v8.b32 "
        "{%0,%1,%2,%3,%4,%5,%6,%7}, [%8];"
        : "=f"(v[0]), "=f"(v[1]), "=f"(v[2]), "=f"(v[3]),
          "=f"(v[4]), "=f"(v[5]), "=f"(v[6]), "=f"(v[7])
        : "l"(p));
}

// colsums are consumed by the epilogue: pin at the protected end of the LRU.
__device__ __forceinline__ void stg_evict_last(float* p, float v, uint64_t pol) {
    asm volatile("st.global.L2::cache_hint.f32 [%0], %1, %2;"
                 :: "l"(p), "f"(v), "l"(pol));
}

// ---------------------------------------------------------------------------
// Epilogue = the R12 measured-best pass2 body, run inline by CTAs 0..127.
// ---------------------------------------------------------------------------
__device__ __forceinline__ void epilogue(int blk, int tid, float* __restrict__ out) {
    const int b    = blk >> 1;
    const int half = blk & 1;

    const float* __restrict__ cse = g_cs_e  + (size_t)b * CC * WW;
    const float* __restrict__ csy = g_cs_ey + (size_t)b * CC * WW;

    __shared__ float sA[4][WW];
    __shared__ float rs[WW];

    const int w  = tid & 127;
    const int cg = tid >> 7;                    // 0..3
    float a[16];
#pragma unroll
    for (int k = 0; k < 16; k++)
        a[k] = cse[(cg + 4 * k) * WW + w];

    const int warp = tid >> 5;                  // 0..15
    const int lane = tid & 31;
    float pe[2][4], py[2][4];
#pragma unroll
    for (int i = 0; i < 2; i++) {
        const int c = half * 32 + warp * 2 + i;
#pragma unroll
        for (int j = 0; j < 4; j++) {
            const int ww = lane + 32 * j;
            pe[i][j] = cse[c * WW + ww];
            py[i][j] = csy[c * WW + ww];
        }
    }

    {
        float s = 0.f;
#pragma unroll
        for (int k = 0; k < 16; k++) s += a[k];
        sA[cg][w] = s;
    }
    __syncthreads();
    if (tid < WW)
        rs[tid] = 1.0f / (sA[0][tid] + sA[1][tid] + sA[2][tid] + sA[3][tid]);
    __syncthreads();

    const float inv127 = 1.0f / 127.0f;
#pragma unroll
    for (int i = 0; i < 2; i++) {
        const int c = half * 32 + warp * 2 + i;
        float xx = 0.f, xy = 0.f;
#pragma unroll
        for (int j = 0; j < 4; j++) {
            const int ww = lane + 32 * j;
            const float r = rs[ww];
            xx += pe[i][j] * ((float)ww * inv127) * r;
            xy += py[i][j] * r;
        }
#pragma unroll
        for (int o = 16; o; o >>= 1) {
            xx += __shfl_xor_sync(0xffffffffu, xx, o);
            xy += __shfl_xor_sync(0xffffffffu, xy, o);
        }
        if (lane == 0) {
            out[((size_t)b * CC + c) * 2 + 0] = xx;
            out[((size_t)b * CC + c) * 2 + 1] = xy;
        }
    }
}

// ---------------------------------------------------------------------------
// Fused persistent kernel (R15 structure, 256-bit loads):
//   thread (hs=warp, half=l>>4, c8=l&15): load j (j=0..3) covers row
//   2*hs + half + 32*j, cols 8*c8..8*c8+7 in ONE ld.v8 (evict_first).
//   Two-deep register pipeline: load j+1 issues before processing j.
//   Column partials: 8 ae + 8 ay per thread; the two half-warps merge via
//   shfl_xor(16) before the smem combine. Barrier-free exp (exp(-m) scale),
//   single barrier/slab, parity-buffered combine, end-of-loop spin fusion.
// ---------------------------------------------------------------------------
__global__ __launch_bounds__(512, 2)
void sam_fused(const float* __restrict__ x, float* __restrict__ out) {
    const int tid  = threadIdx.x;
    const int lane = tid & 31;
    const int hs   = tid >> 5;                  // warp id 0..15
    const int half = lane >> 4;                 // 0/1
    const int c8   = lane & 15;                 // float8 column 0..15

    __shared__ float  smax[2][16];
    __shared__ float4 se[2][16][32];            // [parity][warp][128 floats]
    __shared__ float4 sy[2][16][32];

    const char* __restrict__ xb = reinterpret_cast<const char*>(x);
    const float inv127 = 1.0f / 127.0f;
    const uint64_t pl = pol_evict_last();

    // per-thread byte offset within a slab: row0 = 2*hs + half, col byte = 32*c8
    const int toff = (2 * hs + half) * (WW * 4) + c8 * 32;

    int bc = blockIdx.x;
    int p  = 0;
    if (tid == 0 && bc < NSLAB && bc + GRID1 < NSLAB)
        l2_prefetch_64k(xb + (size_t)(bc + GRID1) * 65536);

    for (; bc < NSLAB; bc += GRID1, p ^= 1) {
        if (tid == 0 && bc + 2 * GRID1 < NSLAB)
            l2_prefetch_64k(xb + (size_t)(bc + 2 * GRID1) * 65536);

        const char* g = xb + (size_t)bc * 65536 + toff;

        float v0[8], v1[8];
        float ae[8] = {0.f,0.f,0.f,0.f,0.f,0.f,0.f,0.f};
        float ay[8] = {0.f,0.f,0.f,0.f,0.f,0.f,0.f,0.f};
        float m = -1e30f;

        ldg_v8_ef(g, v0);                       // j=0 (rows 0..31 band)
#pragma unroll
        for (int j = 0; j < 4; j++) {
            float* cur = (j & 1) ? v1 : v0;
            if (j < 3)                           // pipeline next 256-bit load
                ldg_v8_ef(g + (j + 1) * (32 * WW * 4), (j & 1) ? v0 : v1);
            const float wy = (float)(2 * hs + half + 32 * j) * inv127;
#pragma unroll
            for (int k = 0; k < 8; k++) {
                m = fmaxf(m, cur[k]);
                float e = __expf(cur[k]);
                ae[k] += e;
                ay[k] += e * wy;
            }
        }

        // merge the two half-warps (same c8, different rows)
#pragma unroll
        for (int k = 0; k < 8; k++) {
            ae[k] += __shfl_xor_sync(0xffffffffu, ae[k], 16);
            ay[k] += __shfl_xor_sync(0xffffffffu, ay[k], 16);
        }
        // warp max
#pragma unroll
        for (int o = 16; o; o >>= 1)
            m = fmaxf(m, __shfl_xor_sync(0xffffffffu, m, o));

        if (lane == 0) smax[p][hs] = m;
        if (half == 0) {
            se[p][hs][c8 * 2 + 0] = make_float4(ae[0], ae[1], ae[2], ae[3]);
            se[p][hs][c8 * 2 + 1] = make_float4(ae[4], ae[5], ae[6], ae[7]);
            sy[p][hs][c8 * 2 + 0] = make_float4(ay[0], ay[1], ay[2], ay[3]);
            sy[p][hs][c8 * 2 + 1] = make_float4(ay[4], ay[5], ay[6], ay[7]);
        }
        __syncthreads();                        // single barrier per slab

        // ---- combine (tid<256); others run ahead into next slab's loads ----
        if (tid < 256) {
            float mc = smax[p][0];
#pragma unroll
            for (int k = 1; k < 16; k++) mc = fmaxf(mc, smax[p][k]);
            const float scale = __expf(-mc);

            if (tid < 128) {
                const float* q = reinterpret_cast<const float*>(se[p]);
                float s = 0.f;
#pragma unroll
                for (int k = 0; k < 16; k++) s += q[k * 128 + tid];
                stg_evict_last(&g_cs_e[(size_t)bc * WW + tid], s * scale, pl);
            } else {
                const int w = tid - 128;
                const float* q = reinterpret_cast<const float*>(sy[p]);
                float s = 0.f;
#pragma unroll
                for (int k = 0; k < 16; k++) s += q[k * 128 + w];
                stg_evict_last(&g_cs_ey[(size_t)bc * WW + w], s * scale, pl);
            }
        }
    }

    // ---- grid-wide completion: one release + atomic per CTA ----
    __syncthreads();
    const int blk = blockIdx.x;
    if (tid == 0) {
        __threadfence();                        // release this CTA's colsums
        unsigned old = atomicAdd(&g_done, 1u);
        unsigned target = (old / GRID1 + 1u) * GRID1;   // this launch's 296th
        if (blk < 2 * BB) {
            volatile unsigned* vd = &g_done;
            while (*vd < target) __nanosleep(64);
            __threadfence();                    // acquire all CTAs' colsums
        }
    }
    if (blk >= 2 * BB) return;                  // uniform per CTA: safe
    __syncthreads();                            // all threads see completion

    epilogue(blk, tid, out);
}

extern "C" void kernel_launch(void* const* d_in, const int* in_sizes, int n_in,
                              void* d_out, int out_size) {
    const float* x = (const float*)d_in[0];
    float* out = (float*)d_out;
    sam_fused<<<GRID1, 512>>>(x, out);
}